// round 14
// baseline (speedup 1.0000x reference)
#include <cuda_runtime.h>
#include <cuda_fp16.h>
#include <cstdint>

// ============================================================================
// BCQLinear: y = (x[:, in_reorder] @ dequant(qweight))[:, out_reorder]
// M=128, K=N=4096, WBITS=3, GS=OFI=128.
// R14 = R13 with the dequantw PRMT selector fixed:
//   __byte_perm uses only selector bits [15:0]; R13 put vhi at bits[27:24]
//   (ignored) and vlo in the wrong nibble. Correct:
//   sel = 0x0404 | (vlo<<4) | (vhi<<12)  (byte0=0x00, byte1=hi(q'(vlo)), ...).
// Structure: dequantw builds B' = fp16(q'·alpha) (32MB, GEMM-ready tiles);
//   GEMM = pure fp16 HMMA from smem; rank-1 (alpha+beta)·Xsum in reduce.
// ============================================================================

#define M_TOK   128
#define IN_F    4096
#define OUT_F   4096
#define NGRP    32
#define NPLANE  8

// Scratch (static __device__ — no allocations)
__device__ uint4    g_xa[NGRP * 8 * 8 * 32];             // 1 MB  A frags (fp16)
__device__ uint4    g_bw[1024 * 2048];                   // 32 MB B' fp16 tiles
__device__ float    g_xsum[NGRP * M_TOK];                // 16 KB group row-sums
__device__ float    g_t_part[NPLANE * M_TOK * OUT_F];    // 16 MB K-split partials
__device__ float    g_t_sum[M_TOK * OUT_F];              // 2 MB  reduced sum

__device__ __forceinline__ uint32_t smem_u32(const void* p) {
    uint32_t a;
    asm("{ .reg .u64 t; cvta.to.shared.u64 t, %1; cvt.u32.u64 %0, t; }"
        : "=r"(a) : "l"(p));
    return a;
}
__device__ __forceinline__ void cp_async16(uint32_t saddr, const void* gptr) {
    asm volatile("cp.async.cg.shared.global [%0], [%1], 16;"
                 :: "r"(saddr), "l"(gptr));
}
#define CP_COMMIT() asm volatile("cp.async.commit_group;" ::: "memory")
#define CP_WAIT0()  asm volatile("cp.async.wait_group 0;" ::: "memory")

// spread 8 bits so bit t lands at bit 4t
__device__ __forceinline__ uint32_t spread8(uint32_t x) {
    x = (x | (x << 12)) & 0x000F000Fu;
    x = (x | (x << 6))  & 0x03030303u;
    x = (x | (x << 3))  & 0x11111111u;
    return x;
}

// fp16 LUT for q' = 2v-8, v=0..7: {-8,-6,-4,-2,0,2,4,6}
//   hi bytes: C8 C6 C4 C0 | 00 40 44 46 ; lo bytes all 0x00.
#define QLUT_A 0xC0C4C6C8u
#define QLUT_B 0x46444000u

// ---------------------------------------------------------------------------
// Kernel 1: gather x[:, in_reorder] -> fp16 A fragments (m16n8k16).
// g_xa[((g*8+ks)*8+mtile)*32 + lane] = {a0,a1,a2,a3}
// ---------------------------------------------------------------------------
__global__ __launch_bounds__(256)
void prep_x_kernel(const float* __restrict__ x, const int* __restrict__ in_reorder) {
    const int t    = blockIdx.x * 256 + threadIdx.x;     // 65536 threads
    const int lane = t & 31;
    const int mt   = (t >> 5) & 7;
    const int ks   = (t >> 8) & 7;
    const int g    = t >> 11;
    const int r0   = mt * 16 + (lane >> 2);
    const int kb   = g * 128 + ks * 16 + (lane & 3) * 2;
    const int kk[4] = { kb, kb + 1, kb + 8, kb + 9 };
    uint32_t hi[4] = {0, 0, 0, 0};
    #pragma unroll
    for (int j = 0; j < 4; j++) {
        const int p = __ldg(&in_reorder[kk[j]]);
        const __half ha = __float2half_rn(x[ r0      * IN_F + p]);
        const __half hb = __float2half_rn(x[(r0 + 8) * IN_F + p]);
        const int reg = (j >> 1) * 2;
        const int sh  = (j & 1) * 16;
        hi[reg]     |= (uint32_t)__half_as_ushort(ha) << sh;
        hi[reg + 1] |= (uint32_t)__half_as_ushort(hb) << sh;
    }
    g_xa[((g * 8 + ks) * 8 + mt) * 32 + lane] = make_uint4(hi[0], hi[1], hi[2], hi[3]);
}

// ---------------------------------------------------------------------------
// Kernel 2: Xsum[g][m] = sum_{k in group g} x[m][in_reorder[k]]
// ---------------------------------------------------------------------------
__global__ __launch_bounds__(256)
void xsum_kernel(const float* __restrict__ x, const int* __restrict__ in_reorder) {
    const int m    = blockIdx.x;
    const int tid  = threadIdx.x;
    const int g    = tid >> 3;
    const int part = tid & 7;
    float s = 0.f;
    #pragma unroll
    for (int j = 0; j < 16; j++)
        s += x[m * IN_F + __ldg(&in_reorder[g * 128 + part * 16 + j])];
    s += __shfl_xor_sync(0xffffffffu, s, 1);
    s += __shfl_xor_sync(0xffffffffu, s, 2);
    s += __shfl_xor_sync(0xffffffffu, s, 4);
    if (part == 0) g_xsum[g * 128 + m] = s;
}

// ---------------------------------------------------------------------------
// Kernel 3: dequantw — qweight bit-planes + alpha -> fp16 B' tiles.
// Tile (g,nb) = 2048 uint4 (32KB). chunk = (ks*2+p)*128 + nq*32 + o*4 + r
// chunk word nt = f16x2{ q'(k=16ks+2r+8p, c)·a , q'(k+1, c)·a },
//   c = nb*128 + nq*32 + nt*8 + o.
// ---------------------------------------------------------------------------
__global__ __launch_bounds__(256)
void dequantw_kernel(const int* __restrict__ qweight,
                     const float* __restrict__ alpha,
                     const int* __restrict__ offset) {
    __shared__ uint32_t asm_[256];            // alpha f16x2 for the 2 tiles
    const int tid    = threadIdx.x;
    const int r      = tid & 3;
    const int nq     = (tid >> 2) & 3;
    const int ks     = (tid >> 4) & 7;
    const int tile_l = tid >> 7;
    const int tile   = blockIdx.x * 2 + tile_l;          // g*32 + nb

    // stage alpha as f16x2 (both halves identical): asm_[tile_l*128 + c_l]
    {
        const int tl = tid >> 7, cl = tid & 127;
        const int tt = blockIdx.x * 2 + tl;
        const int g = tt >> 5, nb = tt & 31;
        const float a = __ldg(&alpha[g * OUT_F + nb * 128 + cl]);
        uint32_t a2;
        asm("cvt.rn.f16x2.f32 %0, %1, %1;" : "=r"(a2) : "f"(a));
        asm_[tid] = a2;
    }
    __syncthreads();

    const int* src = qweight + __ldg(&offset[tile]);
    uint32_t p0[4], p1[4], p2[4];
    #pragma unroll
    for (int ki = 0; ki < 4; ki++) {
        const int i    = ks * 16 + 2 * r + (ki & 1) + ((ki >> 1) << 3);
        const int widx = i * 4 + nq;
        p0[ki] = (uint32_t)__ldg(src + widx);
        p1[ki] = (uint32_t)__ldg(src + widx + 512);
        p2[ki] = (uint32_t)__ldg(src + widx + 1024);
    }
    // nib[nt][ki]: nibble o = v(k_i, c = nq*32 + nt*8 + o)
    uint32_t nib[4][4];
    #pragma unroll
    for (int nt = 0; nt < 4; nt++)
        #pragma unroll
        for (int ki = 0; ki < 4; ki++)
            nib[nt][ki] = spread8((p0[ki] >> (nt * 8)) & 0xFFu)
                        | (spread8((p1[ki] >> (nt * 8)) & 0xFFu) << 1)
                        | (spread8((p2[ki] >> (nt * 8)) & 0xFFu) << 2);

    uint4* dst = g_bw + (size_t)tile * 2048;
    const uint32_t* amy = asm_ + tile_l * 128 + nq * 32;
    #pragma unroll
    for (int o = 0; o < 8; o++) {
        #pragma unroll
        for (int p = 0; p < 2; p++) {
            uint32_t w[4];
            #pragma unroll
            for (int nt = 0; nt < 4; nt++) {
                const uint32_t vlo = (nib[nt][2 * p]     >> (4 * o)) & 7u;
                const uint32_t vhi = (nib[nt][2 * p + 1] >> (4 * o)) & 7u;
                // FIXED selector: byte0=0x00(sel 4), byte1=hi(q'(vlo)) (sel vlo),
                //                 byte2=0x00(sel 4), byte3=hi(q'(vhi)) (sel vhi)
                const uint32_t sel = 0x0404u | (vlo << 4) | (vhi << 12);
                uint32_t b = __byte_perm(QLUT_A, QLUT_B, sel);
                asm("mul.rn.f16x2 %0, %0, %1;" : "+r"(b) : "r"(amy[nt * 8 + o]));
                w[nt] = b;
            }
            dst[(ks * 2 + p) * 128 + nq * 32 + o * 4 + r] =
                make_uint4(w[0], w[1], w[2], w[3]);
        }
    }
}

// ---------------------------------------------------------------------------
// Kernel 4: pure fp16 GEMM from smem. grid (32 nb, 16 = mhalf*8+split),
// 256 thr, 96KB dyn smem (A 2x16K @0, B' 2x32K @32768), 2 CTA/SM.
// Per warp-kstep: 2 A LDS.128 + 2 B LDS.128 + 8 HMMA. No epilogue.
// ---------------------------------------------------------------------------
#define SMA_OFF(b) ((b) * 16384)
#define SMB_OFF(b) (32768 + (b) * 32768)

__global__ __launch_bounds__(256, 2)
void bcq_gemm_kernel()
{
    extern __shared__ char sm[];
    const uint32_t smb = smem_u32(sm);
    const int tid  = threadIdx.x;
    const int lane = tid & 31;
    const int wid  = tid >> 5;
    const int nb    = blockIdx.x;
    const int mhalf = blockIdx.y >> 3;
    const int split = blockIdx.y & 7;
    const int wm = wid & 1;
    const int nq = wid >> 1;
    const int r = lane & 3, o = lane >> 2;
    const int bchunk = nq * 32 + o * 4 + r;              // + (ks*2+p)*128
    const int aks = tid >> 5, au = tid & 31;

    float accT[2][4][4];
    #pragma unroll
    for (int a = 0; a < 2; a++)
        #pragma unroll
        for (int b = 0; b < 4; b++)
            #pragma unroll
            for (int c = 0; c < 4; c++) accT[a][b][c] = 0.f;

    // prologue: group 0 tiles
    {
        const int g0 = split * 4;
        const uint4* asrc = g_xa + ((g0 * 8 + aks) * 8 + mhalf * 4) * 32 + au * 4;
        const uint32_t ad = smb + SMA_OFF(0) + aks * 2048 + au * 64;
        #pragma unroll
        for (int j = 0; j < 4; j++) cp_async16(ad + j * 16, asrc + j);
        const uint4* bsrc = g_bw + (size_t)(g0 * 32 + nb) * 2048 + tid * 8;
        const uint32_t bd = smb + SMB_OFF(0) + tid * 128;
        #pragma unroll
        for (int j = 0; j < 8; j++) cp_async16(bd + j * 16, bsrc + j);
        CP_COMMIT();
    }

    for (int gi = 0; gi < 4; gi++) {
        CP_WAIT0();
        __syncthreads();

        if (gi < 3) {
            const int gn = split * 4 + gi + 1;
            const int buf = (gi + 1) & 1;
            const uint4* asrc = g_xa + ((gn * 8 + aks) * 8 + mhalf * 4) * 32 + au * 4;
            const uint32_t ad = smb + SMA_OFF(buf) + aks * 2048 + au * 64;
            #pragma unroll
            for (int j = 0; j < 4; j++) cp_async16(ad + j * 16, asrc + j);
            const uint4* bsrc = g_bw + (size_t)(gn * 32 + nb) * 2048 + tid * 8;
            const uint32_t bd = smb + SMB_OFF(buf) + tid * 128;
            #pragma unroll
            for (int j = 0; j < 8; j++) cp_async16(bd + j * 16, bsrc + j);
            CP_COMMIT();
        }

        const uint4* As = (const uint4*)(sm + SMA_OFF(gi & 1));
        const uint4* Bs = (const uint4*)(sm + SMB_OFF(gi & 1));

        #pragma unroll
        for (int ks = 0; ks < 8; ks++) {
            uint32_t A[2][4];
            #pragma unroll
            for (int mt = 0; mt < 2; mt++) {
                const uint4 h = As[ks * 128 + (wm * 2 + mt) * 32 + lane];
                A[mt][0] = h.x; A[mt][1] = h.y; A[mt][2] = h.z; A[mt][3] = h.w;
            }
            uint32_t B[4][2];
            #pragma unroll
            for (int p = 0; p < 2; p++) {
                const uint4 w = Bs[(ks * 2 + p) * 128 + bchunk];
                B[0][p] = w.x; B[1][p] = w.y; B[2][p] = w.z; B[3][p] = w.w;
            }
            #pragma unroll
            for (int mt = 0; mt < 2; mt++)
                #pragma unroll
                for (int nt = 0; nt < 4; nt++)
                    asm volatile(
                        "mma.sync.aligned.m16n8k16.row.col.f32.f16.f16.f32 "
                        "{%0,%1,%2,%3}, {%4,%5,%6,%7}, {%8,%9}, {%0,%1,%2,%3};"
                        : "+f"(accT[mt][nt][0]), "+f"(accT[mt][nt][1]),
                          "+f"(accT[mt][nt][2]), "+f"(accT[mt][nt][3])
                        : "r"(A[mt][0]), "r"(A[mt][1]), "r"(A[mt][2]), "r"(A[mt][3]),
                          "r"(B[nt][0]), "r"(B[nt][1]));
        }
    }

    // write K-split partials, plane = split (deterministic)
    float* dst = g_t_part + (size_t)split * (M_TOK * OUT_F);
    #pragma unroll
    for (int mt = 0; mt < 2; mt++) {
        const int row0 = mhalf * 64 + wm * 32 + mt * 16 + (lane >> 2);
        #pragma unroll
        for (int nt = 0; nt < 4; nt++) {
            const int col = nb * 128 + nq * 32 + nt * 8 + (lane & 3) * 2;
            *(float2*)&dst[ row0      * OUT_F + col] =
                make_float2(accT[mt][nt][0], accT[mt][nt][1]);
            *(float2*)&dst[(row0 + 8) * OUT_F + col] =
                make_float2(accT[mt][nt][2], accT[mt][nt][3]);
        }
    }
}

// ---------------------------------------------------------------------------
// Kernel 5: reduce 8 planes + rank-1 term sum_g Xsum[g][m]·(alpha+beta)[g][n]
// ---------------------------------------------------------------------------
__global__ __launch_bounds__(256)
void reduce_kernel(const float* __restrict__ alpha, const float* __restrict__ beta) {
    const int i = blockIdx.x * 256 + threadIdx.x;        // 131072
    const int m = i >> 10;
    const int n4 = i & 1023;
    const float4* p = (const float4*)g_t_part;
    float4 s = p[i];
    #pragma unroll
    for (int pl = 1; pl < NPLANE; pl++) {
        const float4 t = p[pl * 131072 + i];
        s.x += t.x; s.y += t.y; s.z += t.z; s.w += t.w;
    }
    const float4* a4 = (const float4*)alpha;
    const float4* b4 = (const float4*)beta;
    #pragma unroll 8
    for (int g = 0; g < NGRP; g++) {
        const float xs = __ldg(&g_xsum[g * 128 + m]);
        const float4 av = __ldg(&a4[g * 1024 + n4]);
        const float4 bv = __ldg(&b4[g * 1024 + n4]);
        s.x = fmaf(xs, av.x + bv.x, s.x);
        s.y = fmaf(xs, av.y + bv.y, s.y);
        s.z = fmaf(xs, av.z + bv.z, s.z);
        s.w = fmaf(xs, av.w + bv.w, s.w);
    }
    ((float4*)g_t_sum)[i] = s;
}

// ---------------------------------------------------------------------------
// Kernel 6: output permutation — coalesced writes, 4 independent gathers
// ---------------------------------------------------------------------------
__global__ __launch_bounds__(256)
void permute_kernel(const int* __restrict__ out_reorder, float* __restrict__ y) {
    const int t = blockIdx.x * 256 + threadIdx.x;        // 131072
    const int c = t & 4095;
    const int mq = t >> 12;                              // 0..31
    const int n = __ldg(&out_reorder[c]);
    #pragma unroll
    for (int u = 0; u < 4; u++) {
        const int m = mq * 4 + u;
        y[(size_t)m * OUT_F + c] = g_t_sum[(m << 12) | n];
    }
}

// ---------------------------------------------------------------------------
// Launch
// ---------------------------------------------------------------------------
extern "C" void kernel_launch(void* const* d_in, const int* in_sizes, int n_in,
                              void* d_out, int out_size) {
    const float* x           = (const float*)d_in[0];
    const int*   qweight     = (const int*)  d_in[1];
    const float* alpha       = (const float*)d_in[2];
    const float* beta        = (const float*)d_in[3];
    // d_in[4] = block_bitwidth (uniform 3, unused)
    const int*   offset      = (const int*)  d_in[5];
    const int*   in_reorder  = (const int*)  d_in[6];
    const int*   out_reorder = (const int*)  d_in[7];
    float* y = (float*)d_out;

    cudaFuncSetAttribute(bcq_gemm_kernel,
                         cudaFuncAttributeMaxDynamicSharedMemorySize, 98304);

    prep_x_kernel<<<256, 256>>>(x, in_reorder);
    xsum_kernel<<<128, 256>>>(x, in_reorder);
    dequantw_kernel<<<512, 256>>>(qweight, alpha, offset);
    bcq_gemm_kernel<<<dim3(32, 16), 256, 98304>>>();
    reduce_kernel<<<512, 256>>>(alpha, beta);
    permute_kernel<<<512, 256>>>(out_reorder, y);
}

// round 16
// speedup vs baseline: 1.4542x; 1.4542x over previous
#include <cuda_runtime.h>
#include <cuda_fp16.h>
#include <cstdint>

// ============================================================================
// BCQLinear: y = (x[:, in_reorder] @ dequant(qweight))[:, out_reorder]
// M=128, K=N=4096, WBITS=3, GS=OFI=128.
// R16 == R15 resubmit (R15 died in the GB300 broker before reaching the GPU).
// Big-tile fused GEMM: CTA = M128 x N256 (2 out-blocks), 512 thr,
//   grid (16,8) = 128 CTAs = ONE wave, 1 CTA/SM, 128KB smem double-buffered.
//   B consumed as bytes (16KB/tile) with R12-proven PRMT+HMUL2 alpha-folded
//   dequant: per warp-kstep ~41 issues vs 16 HMMA -> tensor-bound.
//   No dequantw kernel. Rank-1 (alpha+beta)·Xsum in GEMM group-epilogue.
//   q' = 2v-8 exact fp16; q = q'+1 compensated by the rank-1 term.
// ============================================================================

#define M_TOK   128
#define IN_F    4096
#define OUT_F   4096
#define NGRP    32
#define NPLANE  8

// Scratch (static __device__ — no allocations)
__device__ uint4    g_xa[NGRP * 8 * 8 * 32];             // 1 MB  A frags (fp16)
__device__ uint32_t g_qb[1024 * 4096];                   // 16 MB B bytes, frag order
__device__ float    g_xsum[NGRP * M_TOK];                // 16 KB group row-sums
__device__ float    g_t_part[NPLANE * M_TOK * OUT_F];    // 16 MB K-split partials
__device__ float    g_t_sum[M_TOK * OUT_F];              // 2 MB  reduced sum

__device__ __forceinline__ uint32_t smem_u32(const void* p) {
    uint32_t a;
    asm("{ .reg .u64 t; cvta.to.shared.u64 t, %1; cvt.u32.u64 %0, t; }"
        : "=r"(a) : "l"(p));
    return a;
}
__device__ __forceinline__ void cp_async16(uint32_t saddr, const void* gptr) {
    asm volatile("cp.async.cg.shared.global [%0], [%1], 16;"
                 :: "r"(saddr), "l"(gptr));
}
#define CP_COMMIT() asm volatile("cp.async.commit_group;" ::: "memory")
#define CP_WAIT0()  asm volatile("cp.async.wait_group 0;" ::: "memory")

// spread 8 bits so bit t lands at bit 4t
__device__ __forceinline__ uint32_t spread8(uint32_t x) {
    x = (x | (x << 12)) & 0x000F000Fu;
    x = (x | (x << 6))  & 0x03030303u;
    x = (x | (x << 3))  & 0x11111111u;
    return x;
}

// fp16 LUT for q' = 2v-8, v=0..7: {-8,-6,-4,-2,0,2,4,6}
//   hi bytes: C8 C6 C4 C0 | 00 40 44 46 ; lo bytes all 0x00.
#define QLUT_A 0xC0C4C6C8u
#define QLUT_B 0x46444000u

// ---------------------------------------------------------------------------
// Kernel 1: gather x[:, in_reorder] -> fp16 A fragments (m16n8k16).
// g_xa[((g*8+ks)*8+mtile)*32 + lane] = {a0,a1,a2,a3}
// ---------------------------------------------------------------------------
__global__ __launch_bounds__(256)
void prep_x_kernel(const float* __restrict__ x, const int* __restrict__ in_reorder) {
    const int t    = blockIdx.x * 256 + threadIdx.x;     // 65536 threads
    const int lane = t & 31;
    const int mt   = (t >> 5) & 7;
    const int ks   = (t >> 8) & 7;
    const int g    = t >> 11;
    const int r0   = mt * 16 + (lane >> 2);
    const int kb   = g * 128 + ks * 16 + (lane & 3) * 2;
    const int kk[4] = { kb, kb + 1, kb + 8, kb + 9 };
    uint32_t hi[4] = {0, 0, 0, 0};
    #pragma unroll
    for (int j = 0; j < 4; j++) {
        const int p = __ldg(&in_reorder[kk[j]]);
        const __half ha = __float2half_rn(x[ r0      * IN_F + p]);
        const __half hb = __float2half_rn(x[(r0 + 8) * IN_F + p]);
        const int reg = (j >> 1) * 2;
        const int sh  = (j & 1) * 16;
        hi[reg]     |= (uint32_t)__half_as_ushort(ha) << sh;
        hi[reg + 1] |= (uint32_t)__half_as_ushort(hb) << sh;
    }
    g_xa[((g * 8 + ks) * 8 + mt) * 32 + lane] = make_uint4(hi[0], hi[1], hi[2], hi[3]);
}

// ---------------------------------------------------------------------------
// Kernel 2: Xsum[g][m] = sum_{k in group g} x[m][in_reorder[k]]
// ---------------------------------------------------------------------------
__global__ __launch_bounds__(256)
void xsum_kernel(const float* __restrict__ x, const int* __restrict__ in_reorder) {
    const int m    = blockIdx.x;
    const int tid  = threadIdx.x;
    const int g    = tid >> 3;
    const int part = tid & 7;
    float s = 0.f;
    #pragma unroll
    for (int j = 0; j < 16; j++)
        s += x[m * IN_F + __ldg(&in_reorder[g * 128 + part * 16 + j])];
    s += __shfl_xor_sync(0xffffffffu, s, 1);
    s += __shfl_xor_sync(0xffffffffu, s, 2);
    s += __shfl_xor_sync(0xffffffffu, s, 4);
    if (part == 0) g_xsum[g * 128 + m] = s;
}

// ---------------------------------------------------------------------------
// Kernel 3: repack bit-planes -> BYTE layout in B-frag order (R11, proven).
// Word at [tile][chunk16][nt]: bytes [k0,k1,k8,k9], chunk-swizzled (nq+r)&3.
// ---------------------------------------------------------------------------
__global__ __launch_bounds__(256)
void repack_kernel(const int* __restrict__ qweight, const int* __restrict__ offset) {
    const int t    = blockIdx.x * 256 + threadIdx.x;     // 131072
    const int nq   = t & 3;
    const int r    = (t >> 2) & 3;
    const int ks   = (t >> 4) & 7;
    const int tile = t >> 7;                             // g*32 + nb
    const int* src = qweight + __ldg(&offset[tile]);

    uint32_t p0[4], p1[4], p2[4];
    #pragma unroll
    for (int ki = 0; ki < 4; ki++) {
        const int i    = ks * 16 + 2 * r + (ki & 1) + ((ki >> 1) << 3);
        const int widx = i * 4 + nq;
        p0[ki] = (uint32_t)__ldg(src + widx);
        p1[ki] = (uint32_t)__ldg(src + widx + 512);
        p2[ki] = (uint32_t)__ldg(src + widx + 1024);
    }
    uint32_t nib[4][4];
    #pragma unroll
    for (int nt = 0; nt < 4; nt++)
        #pragma unroll
        for (int ki = 0; ki < 4; ki++)
            nib[nt][ki] = spread8((p0[ki] >> (nt * 8)) & 0xFFu)
                        | (spread8((p1[ki] >> (nt * 8)) & 0xFFu) << 1)
                        | (spread8((p2[ki] >> (nt * 8)) & 0xFFu) << 2);

    uint4* dst = ((uint4*)g_qb) + tile * 1024;
    const int cbase = (((ks * 4 + r) * 8) << 2) + ((nq + r) & 3);
    #pragma unroll
    for (int o = 0; o < 8; o++) {
        uint32_t wds[4];
        #pragma unroll
        for (int nt = 0; nt < 4; nt++)
            wds[nt] = ((nib[nt][0] >> (4 * o)) & 0xFu)
                    | (((nib[nt][1] >> (4 * o)) & 0xFu) << 8)
                    | (((nib[nt][2] >> (4 * o)) & 0xFu) << 16)
                    | (((nib[nt][3] >> (4 * o)) & 0xFu) << 24);
        dst[cbase + o * 4] = make_uint4(wds[0], wds[1], wds[2], wds[3]);
    }
}

// ---------------------------------------------------------------------------
// Kernel 4: big-tile fused GEMM. grid (16 nbp, 8 split), 512 thr, 128KB smem.
// Warp wid: wm = wid&1 (M-half), wn = wid>>1: nbl = wn>>2 (out-block in pair),
// nq = wn&3 (n-quarter). Each warp: M64 x N32 -> 16 HMMA/kstep.
// smem: A 2x32KB @ 0/32768, B 2x32KB @ 65536/98304.
// ---------------------------------------------------------------------------
#define SMA_OFF(b) ((b) * 32768)
#define SMB_OFF(b) (65536 + (b) * 32768)

__global__ __launch_bounds__(512, 1)
void bcq_gemm_kernel(const float* __restrict__ alpha,
                     const float* __restrict__ beta)
{
    extern __shared__ char sm[];
    const uint32_t smb = smem_u32(sm);
    const int tid  = threadIdx.x;
    const int lane = tid & 31;
    const int wid  = tid >> 5;
    const int nbp   = blockIdx.x;             // out-block pair
    const int split = blockIdx.y;
    const int wm  = wid & 1;
    const int wn  = wid >> 1;
    const int nbl = wn >> 2;                  // 0/1 within pair
    const int nq  = wn & 3;
    const int nb  = nbp * 2 + nbl;
    const int r = lane & 3, o = lane >> 2;
    const int boffw = ((((r * 8 + o) << 2) + ((nq + r) & 3)) << 2);  // word units
    // cp.async thread mapping: B uses tile_l = tid>>8, u = tid&255
    const int btl = tid >> 8, bu = tid & 255;

    float accT[4][4][4];
    #pragma unroll
    for (int a = 0; a < 4; a++)
        #pragma unroll
        for (int b = 0; b < 4; b++)
            #pragma unroll
            for (int c = 0; c < 4; c++) accT[a][b][c] = 0.f;

    // prologue: group 0 tiles (A 32KB full-M, B 2x16KB byte tiles)
    {
        const int g0 = split * 4;
        const uint4* asrc = g_xa + g0 * 2048 + tid * 4;
        const uint32_t ad = smb + SMA_OFF(0) + tid * 64;
        #pragma unroll
        for (int j = 0; j < 4; j++) cp_async16(ad + j * 16, asrc + j);
        const uint32_t* bsrc = g_qb + (size_t)(g0 * 32 + nbp * 2 + btl) * 4096 + bu * 16;
        const uint32_t bd = smb + SMB_OFF(0) + btl * 16384 + bu * 64;
        #pragma unroll
        for (int j = 0; j < 4; j++) cp_async16(bd + j * 16, bsrc + j * 4);
        CP_COMMIT();
    }

    for (int gi = 0; gi < 4; gi++) {
        const int g = split * 4 + gi;

        // alpha (f16x2 broadcast) for folding into B: col = nb*128+nq*32+nt*8+o
        uint32_t af[4];
        #pragma unroll
        for (int nt = 0; nt < 4; nt++) {
            const float a = __ldg(&alpha[g * OUT_F + nb * 128 + nq * 32 + nt * 8 + o]);
            asm("cvt.rn.f16x2.f32 %0, %1, %1;" : "=r"(af[nt]) : "f"(a));
        }

        CP_WAIT0();
        __syncthreads();

        if (gi < 3) {
            const int gn = g + 1;
            const int buf = (gi + 1) & 1;
            const uint4* asrc = g_xa + gn * 2048 + tid * 4;
            const uint32_t ad = smb + SMA_OFF(buf) + tid * 64;
            #pragma unroll
            for (int j = 0; j < 4; j++) cp_async16(ad + j * 16, asrc + j);
            const uint32_t* bsrc =
                g_qb + (size_t)(gn * 32 + nbp * 2 + btl) * 4096 + bu * 16;
            const uint32_t bd = smb + SMB_OFF(buf) + btl * 16384 + bu * 64;
            #pragma unroll
            for (int j = 0; j < 4; j++) cp_async16(bd + j * 16, bsrc + j * 4);
            CP_COMMIT();
        }

        const uint4*    As = (const uint4*)(sm + SMA_OFF(gi & 1));
        const uint32_t* Bs = (const uint32_t*)(sm + SMB_OFF(gi & 1)) + nbl * 4096;

        #pragma unroll
        for (int ks = 0; ks < 8; ks++) {
            // --- A frags: 4 x LDS.128 (full M-half, conflict-free) ---
            uint32_t A[4][4];
            #pragma unroll
            for (int mt = 0; mt < 4; mt++) {
                const uint4 h = As[ks * 256 + (wm * 4 + mt) * 32 + lane];
                A[mt][0] = h.x; A[mt][1] = h.y; A[mt][2] = h.z; A[mt][3] = h.w;
            }

            // --- B: ONE LDS.128 -> 4 words (nt), bytes [k0,k1,k8,k9] ---
            const uint4 w = *(const uint4*)(Bs + ks * 512 + boffw);
            const uint32_t wn4[4] = {w.x, w.y, w.z, w.w};

            // --- dequant+scale: PRMT -> q' f16x2, HMUL2 by alpha (R12) ---
            uint32_t B[4][2];
            #pragma unroll
            for (int nt = 0; nt < 4; nt++) {
                uint32_t b0 = __byte_perm(QLUT_A, QLUT_B,
                                          ((wn4[nt] << 4)  & 0xF0F0u) | 0x0404u);
                uint32_t b1 = __byte_perm(QLUT_A, QLUT_B,
                                          ((wn4[nt] >> 12) & 0xF0F0u) | 0x0404u);
                asm("mul.rn.f16x2 %0, %0, %1;" : "+r"(b0) : "r"(af[nt]));
                asm("mul.rn.f16x2 %0, %0, %1;" : "+r"(b1) : "r"(af[nt]));
                B[nt][0] = b0; B[nt][1] = b1;
            }

            // --- 16 fp16 HMMA per warp per kstep ---
            #pragma unroll
            for (int mt = 0; mt < 4; mt++)
                #pragma unroll
                for (int nt = 0; nt < 4; nt++)
                    asm volatile(
                        "mma.sync.aligned.m16n8k16.row.col.f32.f16.f16.f32 "
                        "{%0,%1,%2,%3}, {%4,%5,%6,%7}, {%8,%9}, {%0,%1,%2,%3};"
                        : "+f"(accT[mt][nt][0]), "+f"(accT[mt][nt][1]),
                          "+f"(accT[mt][nt][2]), "+f"(accT[mt][nt][3])
                        : "r"(A[mt][0]), "r"(A[mt][1]), "r"(A[mt][2]), "r"(A[mt][3]),
                          "r"(B[nt][0]), "r"(B[nt][1]));
        }

        // --- group epilogue: accT += (alpha+beta)·Xsum (rank-1, R12-proven) ---
        #pragma unroll
        for (int nt = 0; nt < 4; nt++) {
            const int col = nb * 128 + nq * 32 + nt * 8 + (lane & 3) * 2;
            const float c0 = __ldg(&alpha[g * OUT_F + col]) +
                             __ldg(&beta [g * OUT_F + col]);
            const float c1 = __ldg(&alpha[g * OUT_F + col + 1]) +
                             __ldg(&beta [g * OUT_F + col + 1]);
            #pragma unroll
            for (int mt = 0; mt < 4; mt++) {
                const int row = wm * 64 + mt * 16 + (lane >> 2);
                const float x0 = __ldg(&g_xsum[g * 128 + row]);
                const float x1 = __ldg(&g_xsum[g * 128 + row + 8]);
                accT[mt][nt][0] = fmaf(c0, x0, accT[mt][nt][0]);
                accT[mt][nt][1] = fmaf(c1, x0, accT[mt][nt][1]);
                accT[mt][nt][2] = fmaf(c0, x1, accT[mt][nt][2]);
                accT[mt][nt][3] = fmaf(c1, x1, accT[mt][nt][3]);
            }
        }
    }

    // --- write K-split partials, plane = split (deterministic) ---
    float* dst = g_t_part + (size_t)split * (M_TOK * OUT_F);
    #pragma unroll
    for (int mt = 0; mt < 4; mt++) {
        const int row0 = wm * 64 + mt * 16 + (lane >> 2);
        #pragma unroll
        for (int nt = 0; nt < 4; nt++) {
            const int col = nb * 128 + nq * 32 + nt * 8 + (lane & 3) * 2;
            *(float2*)&dst[ row0      * OUT_F + col] =
                make_float2(accT[mt][nt][0], accT[mt][nt][1]);
            *(float2*)&dst[(row0 + 8) * OUT_F + col] =
                make_float2(accT[mt][nt][2], accT[mt][nt][3]);
        }
    }
}

// ---------------------------------------------------------------------------
// Kernel 5: reduce 8 planes (coalesced float4)
// ---------------------------------------------------------------------------
__global__ __launch_bounds__(256)
void reduce_kernel() {
    const int i = blockIdx.x * 256 + threadIdx.x;        // 131072 float4s
    const float4* p = (const float4*)g_t_part;
    float4 s = p[i];
    #pragma unroll
    for (int pl = 1; pl < NPLANE; pl++) {
        const float4 t = p[pl * 131072 + i];
        s.x += t.x; s.y += t.y; s.z += t.z; s.w += t.w;
    }
    ((float4*)g_t_sum)[i] = s;
}

// ---------------------------------------------------------------------------
// Kernel 6: output permutation — coalesced writes, 4 independent gathers
// ---------------------------------------------------------------------------
__global__ __launch_bounds__(256)
void permute_kernel(const int* __restrict__ out_reorder, float* __restrict__ y) {
    const int t = blockIdx.x * 256 + threadIdx.x;        // 131072
    const int c = t & 4095;
    const int mq = t >> 12;                              // 0..31
    const int n = __ldg(&out_reorder[c]);
    #pragma unroll
    for (int u = 0; u < 4; u++) {
        const int m = mq * 4 + u;
        y[(size_t)m * OUT_F + c] = g_t_sum[(m << 12) | n];
    }
}

// ---------------------------------------------------------------------------
// Launch
// ---------------------------------------------------------------------------
extern "C" void kernel_launch(void* const* d_in, const int* in_sizes, int n_in,
                              void* d_out, int out_size) {
    const float* x           = (const float*)d_in[0];
    const int*   qweight     = (const int*)  d_in[1];
    const float* alpha       = (const float*)d_in[2];
    const float* beta        = (const float*)d_in[3];
    // d_in[4] = block_bitwidth (uniform 3, unused)
    const int*   offset      = (const int*)  d_in[5];
    const int*   in_reorder  = (const int*)  d_in[6];
    const int*   out_reorder = (const int*)  d_in[7];
    float* y = (float*)d_out;

    cudaFuncSetAttribute(bcq_gemm_kernel,
                         cudaFuncAttributeMaxDynamicSharedMemorySize, 131072);

    prep_x_kernel<<<256, 256>>>(x, in_reorder);
    xsum_kernel<<<128, 256>>>(x, in_reorder);
    repack_kernel<<<512, 256>>>(qweight, offset);
    bcq_gemm_kernel<<<dim3(16, 8), 512, 131072>>>(alpha, beta);
    reduce_kernel<<<512, 256>>>();
    permute_kernel<<<512, 256>>>(out_reorder, y);
}